// round 1
// baseline (speedup 1.0000x reference)
#include <cuda_runtime.h>
#include <cuda_bf16.h>

// RankPooling via Woodbury + Neumann series.
//   M = X^T X (128x128) is never formed; v = Ey - E^2y + E^3y - E^4y with
//   E = 2C X^T X evaluated as alternating matvecs X*u (D-dim) and X^T*p (T-dim)
//   against a bf16 SMEM-resident copy of X.  Final w = 2C * X (y - v) in fp32
//   from global (L2-hot second pass).
//
// Shapes: X[b] is [D=768, T=128] row-major (t contiguous), out is [256, 768] f32.

#define DN 768
#define TN 128
#define NW 8
#define NTHREADS 256

// SMEM layout (bytes)
#define OFF_X   0          // bf16 [768][128] = 196608
#define OFF_P   196608     // float[768]     = 3072
#define OFF_QP  199680     // float[8][128]  = 4096 (per-warp X^T p partials)
#define OFF_U   203776     // float[128]     = 512 (current u / final s)
#define OFF_V   204288     // float[128]     = 512 (accumulated v)
#define SMEM_BYTES 204800

static __device__ __forceinline__ float warp_sum(float v) {
    v += __shfl_xor_sync(0xffffffffu, v, 16);
    v += __shfl_xor_sync(0xffffffffu, v, 8);
    v += __shfl_xor_sync(0xffffffffu, v, 4);
    v += __shfl_xor_sync(0xffffffffu, v, 2);
    v += __shfl_xor_sync(0xffffffffu, v, 1);
    return v;
}

__global__ void __launch_bounds__(NTHREADS, 1)
rankpool_kernel(const float* __restrict__ X, float* __restrict__ out) {
    extern __shared__ char smraw[];
    unsigned*  sxw = (unsigned*)(smraw + OFF_X);   // bf16x2 words [768*64]
    uint2*     sx2 = (uint2*)(smraw + OFF_X);      // [768*32]
    float*     sp  = (float*)(smraw + OFF_P);
    float*     sqp = (float*)(smraw + OFF_QP);
    float*     su  = (float*)(smraw + OFF_U);
    float*     sv  = (float*)(smraw + OFF_V);

    const int tid  = threadIdx.x;
    const int warp = tid >> 5;
    const int lane = tid & 31;
    const int b    = blockIdx.x;
    const float* Xb = X + (size_t)b * (DN * TN);
    const float4* Xb4 = (const float4*)Xb;
    const float TWO_C = 2e-5f;

    // init u = y = [1..128], v = 0
    if (tid < TN) { su[tid] = (float)(tid + 1); sv[tid] = 0.f; }

    // ---- Phase A: load X fp32 from global, convert to bf16 into SMEM ----
    #pragma unroll 4
    for (int d = warp; d < DN; d += NW) {
        float4 x = Xb4[d * 32 + lane];
        __nv_bfloat162 lo = __float22bfloat162_rn(make_float2(x.x, x.y));
        __nv_bfloat162 hi = __float22bfloat162_rn(make_float2(x.z, x.w));
        uint2 pk;
        pk.x = *reinterpret_cast<unsigned*>(&lo);
        pk.y = *reinterpret_cast<unsigned*>(&hi);
        sx2[d * 32 + lane] = pk;   // one STS.64 per lane, conflict-free
    }
    __syncthreads();

    // ---- Neumann iterations: t_k = E^k y; v = t1 - t2 + t3 - t4 ----
    #pragma unroll 1
    for (int k = 0; k < 4; k++) {
        // p = X * u   (warp per row, lanes split the 128-wide row)
        const float2* su2 = (const float2*)su;
        #pragma unroll 4
        for (int d = warp; d < DN; d += NW) {
            unsigned w0 = sxw[d * 64 + lane];
            unsigned w1 = sxw[d * 64 + 32 + lane];
            float2 u0 = su2[lane];
            float2 u1 = su2[lane + 32];
            float2 f0 = __bfloat1622float2(*reinterpret_cast<__nv_bfloat162*>(&w0));
            float2 f1 = __bfloat1622float2(*reinterpret_cast<__nv_bfloat162*>(&w1));
            float acc = f0.x * u0.x + f0.y * u0.y + f1.x * u1.x + f1.y * u1.y;
            acc = warp_sum(acc);
            if (lane == 0) sp[d] = acc;
        }
        __syncthreads();

        // qpart[warp] = partial X^T * p over this warp's 96 rows
        {
            float2 a0 = make_float2(0.f, 0.f);
            float2 a1 = make_float2(0.f, 0.f);
            const int d0 = warp * 96;
            #pragma unroll 8
            for (int dd = 0; dd < 96; dd++) {
                const int d = d0 + dd;
                float pd = sp[d];                      // broadcast
                unsigned w0 = sxw[d * 64 + lane];
                unsigned w1 = sxw[d * 64 + 32 + lane];
                float2 f0 = __bfloat1622float2(*reinterpret_cast<__nv_bfloat162*>(&w0));
                float2 f1 = __bfloat1622float2(*reinterpret_cast<__nv_bfloat162*>(&w1));
                a0.x += pd * f0.x; a0.y += pd * f0.y;
                a1.x += pd * f1.x; a1.y += pd * f1.y;
            }
            float2* qp2 = (float2*)(sqp + warp * TN);
            qp2[lane]      = a0;   // t = 2l, 2l+1
            qp2[lane + 32] = a1;   // t = 64+2l, 64+2l+1
        }
        __syncthreads();

        // reduce partials, scale by 2C, update u and v (deterministic)
        if (tid < TN) {
            float q = 0.f;
            #pragma unroll
            for (int w = 0; w < NW; w++) q += sqp[w * TN + tid];
            float t = TWO_C * q;
            su[tid] = t;
            sv[tid] += (k & 1) ? -t : t;
        }
        __syncthreads();
    }

    // s = y - v  (store into su, float4-aligned for phase C)
    if (tid < TN) su[tid] = (float)(tid + 1) - sv[tid];
    __syncthreads();

    // ---- Phase C: w = 2C * X * s, fp32 X re-read from global (L2-hot) ----
    const float4* su4 = (const float4*)su;
    #pragma unroll 4
    for (int d = warp; d < DN; d += NW) {
        float4 x  = Xb4[d * 32 + lane];
        float4 s4 = su4[lane];
        float acc = x.x * s4.x + x.y * s4.y + x.z * s4.z + x.w * s4.w;
        acc = warp_sum(acc);
        if (lane == 0) out[(size_t)b * DN + d] = TWO_C * acc;
    }
}

extern "C" void kernel_launch(void* const* d_in, const int* in_sizes, int n_in,
                              void* d_out, int out_size) {
    (void)in_sizes; (void)n_in; (void)out_size;
    const float* X = (const float*)d_in[0];
    float* out = (float*)d_out;

    cudaFuncSetAttribute(rankpool_kernel,
                         cudaFuncAttributeMaxDynamicSharedMemorySize, SMEM_BYTES);
    rankpool_kernel<<<256, NTHREADS, SMEM_BYTES>>>(X, out);
}

// round 2
// speedup vs baseline: 2.1613x; 2.1613x over previous
#include <cuda_runtime.h>
#include <cuda_bf16.h>

// RankPooling via Woodbury + Neumann series (R2: latency-optimized).
//   w = 2C * X (y - v),  v = Ey - E^2y + E^3y - E^4y,  E = 2C X^T X
// evaluated as alternating matvecs against a bf16 SMEM copy of X.
// Key changes vs R1: pitch-65 smem layout (conflict-free both ways),
// thread-per-row X*u (no shuffle reductions), MLP-8 global load phase.
//
// X[b]: [D=768, T=128] row-major (t contiguous). out: [256, 768] f32.

#define DN 768
#define TN 128
#define NW 8
#define NTHREADS 256
#define PITCH 65   // words per smem row (130 bf16, 260B): lane-stride 65 % 32 == 1

// SMEM layout (bytes)
#define OFF_X   0          // bf16x2 words [768][65] = 199680
#define OFF_P   199680     // float[768]             = 3072
#define OFF_QP  202752     // float[8][128]          = 4096
#define OFF_U   206848     // float[128]             = 512
#define OFF_V   207360     // float[128]             = 512
#define SMEM_BYTES 207872

static __device__ __forceinline__ float warp_sum(float v) {
    v += __shfl_xor_sync(0xffffffffu, v, 16);
    v += __shfl_xor_sync(0xffffffffu, v, 8);
    v += __shfl_xor_sync(0xffffffffu, v, 4);
    v += __shfl_xor_sync(0xffffffffu, v, 2);
    v += __shfl_xor_sync(0xffffffffu, v, 1);
    return v;
}

static __device__ __forceinline__ float2 bf2f(unsigned w) {
    return __bfloat1622float2(*reinterpret_cast<__nv_bfloat162*>(&w));
}

__global__ void __launch_bounds__(NTHREADS, 1)
rankpool_kernel(const float* __restrict__ X, float* __restrict__ out) {
    extern __shared__ char smraw[];
    unsigned* sxw = (unsigned*)(smraw + OFF_X);
    float*    sp  = (float*)(smraw + OFF_P);
    float*    sqp = (float*)(smraw + OFF_QP);
    float*    su  = (float*)(smraw + OFF_U);
    float*    sv  = (float*)(smraw + OFF_V);

    const int tid  = threadIdx.x;
    const int warp = tid >> 5;
    const int lane = tid & 31;
    const int b    = blockIdx.x;
    const float* Xb = X + (size_t)b * (DN * TN);
    const float4* Xb4 = (const float4*)Xb;
    const float TWO_C = 2e-5f;

    if (tid < TN) { su[tid] = (float)(tid + 1); sv[tid] = 0.f; }

    // ---- Phase A: stream X fp32 -> bf16 SMEM, 8 loads in flight/thread ----
    {
        const int dbase = warp * 96;
        #pragma unroll 1
        for (int j = 0; j < 96; j += 8) {
            float4 xs[8];
            #pragma unroll
            for (int k = 0; k < 8; k++)
                xs[k] = Xb4[(dbase + j + k) * 32 + lane];
            #pragma unroll
            for (int k = 0; k < 8; k++) {
                const int d = dbase + j + k;
                __nv_bfloat162 lo = __float22bfloat162_rn(make_float2(xs[k].x, xs[k].y));
                __nv_bfloat162 hi = __float22bfloat162_rn(make_float2(xs[k].z, xs[k].w));
                sxw[d * PITCH + 2 * lane]     = *reinterpret_cast<unsigned*>(&lo);
                sxw[d * PITCH + 2 * lane + 1] = *reinterpret_cast<unsigned*>(&hi);
            }
        }
    }
    __syncthreads();

    // ---- Neumann: t_k = E^k y; v = t1 - t2 + t3 - t4 ----
    #pragma unroll 1
    for (int k = 0; k < 4; k++) {
        // p = X * u : thread-per-row, no reductions.
        // Rows tid, tid+256, tid+512; lane-stride = PITCH % 32 == 1 -> conflict-free.
        {
            const float2* su2 = (const float2*)su;
            const unsigned* r0 = sxw + (size_t)tid * PITCH;
            const unsigned* r1 = r0 + 256 * PITCH;
            const unsigned* r2 = r1 + 256 * PITCH;
            float a0 = 0.f, a1 = 0.f, a2 = 0.f;
            #pragma unroll 8
            for (int i = 0; i < 64; i++) {
                float2 u = su2[i];                 // uniform -> broadcast
                float2 f;
                f = bf2f(r0[i]); a0 += f.x * u.x + f.y * u.y;
                f = bf2f(r1[i]); a1 += f.x * u.x + f.y * u.y;
                f = bf2f(r2[i]); a2 += f.x * u.x + f.y * u.y;
            }
            sp[tid]       = a0;
            sp[tid + 256] = a1;
            sp[tid + 512] = a2;
        }
        __syncthreads();

        // q_part[warp] = partial X^T * p over this warp's 96 rows
        {
            float2 a0 = make_float2(0.f, 0.f);
            float2 a1 = make_float2(0.f, 0.f);
            const int d0 = warp * 96;
            #pragma unroll 8
            for (int dd = 0; dd < 96; dd++) {
                const int d = d0 + dd;
                const unsigned* row = sxw + (size_t)d * PITCH;
                float pd = sp[d];                  // uniform -> broadcast
                float2 f0 = bf2f(row[lane]);
                float2 f1 = bf2f(row[lane + 32]);
                a0.x += pd * f0.x; a0.y += pd * f0.y;
                a1.x += pd * f1.x; a1.y += pd * f1.y;
            }
            float2* qp2 = (float2*)(sqp + warp * TN);
            qp2[lane]      = a0;   // t = 2l, 2l+1
            qp2[lane + 32] = a1;   // t = 64+2l, 64+2l+1
        }
        __syncthreads();

        // reduce partials, update u and v
        if (tid < TN) {
            float q = 0.f;
            #pragma unroll
            for (int w = 0; w < NW; w++) q += sqp[w * TN + tid];
            float t = TWO_C * q;
            su[tid] = t;
            sv[tid] += (k & 1) ? -t : t;
        }
        __syncthreads();
    }

    // s = y - v
    if (tid < TN) su[tid] = (float)(tid + 1) - sv[tid];
    __syncthreads();

    // ---- Phase C: w = 2C * X * s, fp32 X from global (L2-hot), coalesced ----
    const float4* su4 = (const float4*)su;
    #pragma unroll 4
    for (int d = warp; d < DN; d += NW) {
        float4 x  = Xb4[d * 32 + lane];
        float4 s4 = su4[lane];
        float acc = x.x * s4.x + x.y * s4.y + x.z * s4.z + x.w * s4.w;
        acc = warp_sum(acc);
        if (lane == 0) out[(size_t)b * DN + d] = TWO_C * acc;
    }
}

extern "C" void kernel_launch(void* const* d_in, const int* in_sizes, int n_in,
                              void* d_out, int out_size) {
    (void)in_sizes; (void)n_in; (void)out_size;
    const float* X = (const float*)d_in[0];
    float* out = (float*)d_out;

    cudaFuncSetAttribute(rankpool_kernel,
                         cudaFuncAttributeMaxDynamicSharedMemorySize, SMEM_BYTES);
    rankpool_kernel<<<256, NTHREADS, SMEM_BYTES>>>(X, out);
}

// round 4
// speedup vs baseline: 2.9465x; 1.3633x over previous
#include <cuda_runtime.h>
#include <cuda_bf16.h>

// RankPooling via Woodbury + Neumann (R4 = R3 resubmit after infra failure).
//   w = 2C * X (y - v),  v = Ey - E^2y + E^3y,  E = 2C X^T X
// bf16 SMEM-resident X for the Neumann matvecs; fp32 global X for the final
// output matvec (accuracy-critical).  X[b]: [D=768, T=128] row-major.
// 24 warps / 1 CTA per SM; pitch-66 uint2 smem layout (conflict-free).

#define DN 768
#define TN 128
#define NW 24
#define NTHREADS 768
#define NITER 3
#define PITCHW 66   // 4B words per smem row (132 bf16, 264B); even -> uint2 aligned

// SMEM layout (bytes)
#define OFF_X   0          // bf16x2 words [768][66] = 202752
#define OFF_P   202752     // float[768]             = 3072
#define OFF_QP  205824     // float[24][128]         = 12288
#define OFF_U   218112     // float[128]             = 512
#define OFF_V   218624     // float[128]             = 512
#define SMEM_BYTES 219136

static __device__ __forceinline__ float warp_sum(float v) {
    v += __shfl_xor_sync(0xffffffffu, v, 16);
    v += __shfl_xor_sync(0xffffffffu, v, 8);
    v += __shfl_xor_sync(0xffffffffu, v, 4);
    v += __shfl_xor_sync(0xffffffffu, v, 2);
    v += __shfl_xor_sync(0xffffffffu, v, 1);
    return v;
}

static __device__ __forceinline__ float2 bf2f(unsigned w) {
    return __bfloat1622float2(*reinterpret_cast<__nv_bfloat162*>(&w));
}

__global__ void __launch_bounds__(NTHREADS, 1)
rankpool_kernel(const float* __restrict__ X, float* __restrict__ out) {
    extern __shared__ char smraw[];
    uint2*    sx2 = (uint2*)(smraw + OFF_X);
    float*    sp  = (float*)(smraw + OFF_P);
    float*    sqp = (float*)(smraw + OFF_QP);
    float*    su  = (float*)(smraw + OFF_U);
    float*    sv  = (float*)(smraw + OFF_V);

    const int tid  = threadIdx.x;
    const int warp = tid >> 5;
    const int lane = tid & 31;
    const int b    = blockIdx.x;
    const float* Xb = X + (size_t)b * (DN * TN);
    const float4* Xb4 = (const float4*)Xb;
    const float TWO_C = 2e-5f;

    if (tid < TN) { su[tid] = (float)(tid + 1); sv[tid] = 0.f; }

    // ---- Phase A: stream X fp32 -> bf16 SMEM (32 rows/warp, MLP 8) ----
    {
        const int dbase = warp * 32;
        #pragma unroll 1
        for (int j = 0; j < 32; j += 8) {
            float4 xs[8];
            #pragma unroll
            for (int k = 0; k < 8; k++)
                xs[k] = Xb4[(dbase + j + k) * 32 + lane];
            #pragma unroll
            for (int k = 0; k < 8; k++) {
                const int d = dbase + j + k;
                __nv_bfloat162 lo = __float22bfloat162_rn(make_float2(xs[k].x, xs[k].y));
                __nv_bfloat162 hi = __float22bfloat162_rn(make_float2(xs[k].z, xs[k].w));
                uint2 pk;
                pk.x = *reinterpret_cast<unsigned*>(&lo);
                pk.y = *reinterpret_cast<unsigned*>(&hi);
                sx2[(d * PITCHW + 2 * lane) >> 1] = pk;  // word offset 2*lane (t=4l..4l+3)
            }
        }
    }
    __syncthreads();

    // ---- Neumann: t_k = E^k y; v = t1 - t2 + t3 ----
    #pragma unroll 1
    for (int k = 0; k < NITER; k++) {
        // p = X * u : one row per thread, uint2 smem loads, no reductions.
        {
            const float4* su4 = (const float4*)su;
            const uint2* row = sx2 + ((size_t)tid * PITCHW >> 1);
            float acc = 0.f;
            #pragma unroll 8
            for (int i = 0; i < 32; i++) {
                uint2  xw = row[i];
                float4 u4 = su4[i];                 // uniform -> broadcast
                float2 f0 = bf2f(xw.x);
                float2 f1 = bf2f(xw.y);
                acc += f0.x * u4.x + f0.y * u4.y + f1.x * u4.z + f1.y * u4.w;
            }
            sp[tid] = acc;
        }
        __syncthreads();

        // partial q = X^T * p over this warp's 32 rows; lane covers t=4l..4l+3
        {
            float a0 = 0.f, a1 = 0.f, a2 = 0.f, a3 = 0.f;
            const int d0 = warp * 32;
            #pragma unroll 8
            for (int dd = 0; dd < 32; dd++) {
                const int d = d0 + dd;
                float pd = sp[d];                   // uniform -> broadcast
                uint2 xw = sx2[((size_t)d * PITCHW >> 1) + lane];
                float2 f0 = bf2f(xw.x);
                float2 f1 = bf2f(xw.y);
                a0 += pd * f0.x; a1 += pd * f0.y;
                a2 += pd * f1.x; a3 += pd * f1.y;
            }
            float4* qp4 = (float4*)(sqp + warp * TN);
            qp4[lane] = make_float4(a0, a1, a2, a3);
        }
        __syncthreads();

        // reduce 24 partials, update u and v
        if (tid < TN) {
            float q = 0.f;
            #pragma unroll
            for (int w = 0; w < NW; w++) q += sqp[w * TN + tid];
            float t = TWO_C * q;
            su[tid] = t;
            sv[tid] += (k & 1) ? -t : t;
        }
        __syncthreads();
    }

    // s = y - v
    if (tid < TN) su[tid] = (float)(tid + 1) - sv[tid];
    __syncthreads();

    // ---- Phase C: w = 2C * X * s, fp32 X from global (L2-hot), coalesced ----
    {
        const float4* su4 = (const float4*)su;
        const float4 s4 = su4[lane];                // loop-invariant: hoisted
        const int d0 = warp * 32;
        #pragma unroll 4
        for (int j = 0; j < 32; j++) {
            const int d = d0 + j;
            float4 x = Xb4[d * 32 + lane];
            float acc = x.x * s4.x + x.y * s4.y + x.z * s4.z + x.w * s4.w;
            acc = warp_sum(acc);
            if (lane == 0) out[(size_t)b * DN + d] = TWO_C * acc;
        }
    }
}

extern "C" void kernel_launch(void* const* d_in, const int* in_sizes, int n_in,
                              void* d_out, int out_size) {
    (void)in_sizes; (void)n_in; (void)out_size;
    const float* X = (const float*)d_in[0];
    float* out = (float*)d_out;

    cudaFuncSetAttribute(rankpool_kernel,
                         cudaFuncAttributeMaxDynamicSharedMemorySize, SMEM_BYTES);
    rankpool_kernel<<<256, NTHREADS, SMEM_BYTES>>>(X, out);
}

// round 6
// speedup vs baseline: 3.2857x; 1.1151x over previous
#include <cuda_runtime.h>
#include <cuda_bf16.h>

// RankPooling via Woodbury + Neumann (R6 = R5 resubmit after infra failure).
//   w = 2C * (p0 - X*v),  p0 = X*y (fp32, computed during load),
//   v = t1 - t2 + t3,  t1 = 2C X^T p0,  t_{k+1} = 2C X^T (X t_k)  [bf16 smem]
// X[b]: [D=768, T=128] row-major. 24 warps, 1 CTA/SM, pitch-66 uint2 layout.

#define DN 768
#define TN 128
#define NW 24
#define NTHREADS 768
#define NITER 3
#define PITCHW 66   // 4B words per smem row (132 bf16, 264B); even -> uint2 aligned

// SMEM layout (bytes)
#define OFF_X   0          // bf16x2 words [768][66] = 202752
#define OFF_P   202752     // float[768]  (X*u results)      = 3072
#define OFF_P0  205824     // float[768]  (p0 = X*y fp32)    = 3072
#define OFF_QP  208896     // float[24][128]                 = 12288
#define OFF_U   221184     // float[128]                     = 512
#define OFF_V   221696     // float[128]                     = 512
#define SMEM_BYTES 222208

static __device__ __forceinline__ float warp_sum(float v) {
    v += __shfl_xor_sync(0xffffffffu, v, 16);
    v += __shfl_xor_sync(0xffffffffu, v, 8);
    v += __shfl_xor_sync(0xffffffffu, v, 4);
    v += __shfl_xor_sync(0xffffffffu, v, 2);
    v += __shfl_xor_sync(0xffffffffu, v, 1);
    return v;
}

static __device__ __forceinline__ float2 bf2f(unsigned w) {
    return __bfloat1622float2(*reinterpret_cast<__nv_bfloat162*>(&w));
}

__global__ void __launch_bounds__(NTHREADS, 1)
rankpool_kernel(const float* __restrict__ X, float* __restrict__ out) {
    extern __shared__ char smraw[];
    uint2* sx2 = (uint2*)(smraw + OFF_X);
    float* sp  = (float*)(smraw + OFF_P);
    float* sp0 = (float*)(smraw + OFF_P0);
    float* sqp = (float*)(smraw + OFF_QP);
    float* su  = (float*)(smraw + OFF_U);
    float* sv  = (float*)(smraw + OFF_V);

    const int tid  = threadIdx.x;
    const int warp = tid >> 5;
    const int lane = tid & 31;
    const int b    = blockIdx.x;
    const float* Xb = X + (size_t)b * (DN * TN);
    const float4* Xb4 = (const float4*)Xb;
    const float TWO_C = 2e-5f;

    if (tid < TN) sv[tid] = 0.f;

    // y values this lane touches: t = 4*lane .. 4*lane+3 (1-based)
    const float4 y4 = make_float4((float)(4 * lane + 1), (float)(4 * lane + 2),
                                  (float)(4 * lane + 3), (float)(4 * lane + 4));

    // ---- Phase A: stream X fp32 -> bf16 SMEM; fuse p0 = X*y in fp32 ----
    {
        const int dbase = warp * 32;
        #pragma unroll 1
        for (int j = 0; j < 32; j += 8) {
            float4 xs[8];
            #pragma unroll
            for (int k = 0; k < 8; k++)
                xs[k] = Xb4[(dbase + j + k) * 32 + lane];
            #pragma unroll
            for (int k = 0; k < 8; k++) {
                const int d = dbase + j + k;
                __nv_bfloat162 lo = __float22bfloat162_rn(make_float2(xs[k].x, xs[k].y));
                __nv_bfloat162 hi = __float22bfloat162_rn(make_float2(xs[k].z, xs[k].w));
                uint2 pk;
                pk.x = *reinterpret_cast<unsigned*>(&lo);
                pk.y = *reinterpret_cast<unsigned*>(&hi);
                sx2[(d * PITCHW + 2 * lane) >> 1] = pk;
            }
            #pragma unroll
            for (int k = 0; k < 8; k++) {
                float part = xs[k].x * y4.x + xs[k].y * y4.y
                           + xs[k].z * y4.z + xs[k].w * y4.w;
                part = warp_sum(part);
                if (lane == 0) sp0[dbase + j + k] = part;
            }
        }
    }
    __syncthreads();

    // ---- Neumann: v = t1 - t2 + t3 ----
    #pragma unroll 1
    for (int k = 0; k < NITER; k++) {
        if (k > 0) {
            // sp = X * u : one row per thread, uint2 smem loads.
            const float4* su4 = (const float4*)su;
            const uint2* row = sx2 + ((size_t)tid * PITCHW >> 1);
            float acc = 0.f;
            #pragma unroll 8
            for (int i = 0; i < 32; i++) {
                uint2  xw = row[i];
                float4 u4 = su4[i];                 // uniform -> broadcast
                float2 f0 = bf2f(xw.x);
                float2 f1 = bf2f(xw.y);
                acc += f0.x * u4.x + f0.y * u4.y + f1.x * u4.z + f1.y * u4.w;
            }
            sp[tid] = acc;
            __syncthreads();
        }
        const float* psrc = (k == 0) ? sp0 : sp;   // t1 uses exact fp32 p0

        // partial q = X^T * psrc over this warp's 32 rows; lane: t=4l..4l+3
        {
            float a0 = 0.f, a1 = 0.f, a2 = 0.f, a3 = 0.f;
            const int d0 = warp * 32;
            #pragma unroll 8
            for (int dd = 0; dd < 32; dd++) {
                const int d = d0 + dd;
                float pd = psrc[d];                 // uniform -> broadcast
                uint2 xw = sx2[((size_t)d * PITCHW >> 1) + lane];
                float2 f0 = bf2f(xw.x);
                float2 f1 = bf2f(xw.y);
                a0 += pd * f0.x; a1 += pd * f0.y;
                a2 += pd * f1.x; a3 += pd * f1.y;
            }
            float4* qp4 = (float4*)(sqp + warp * TN);
            qp4[lane] = make_float4(a0, a1, a2, a3);
        }
        __syncthreads();

        // reduce 24 partials, update u and v
        if (tid < TN) {
            float q = 0.f;
            #pragma unroll
            for (int w = 0; w < NW; w++) q += sqp[w * TN + tid];
            float t = TWO_C * q;
            su[tid] = t;
            sv[tid] += (k & 1) ? -t : t;
        }
        __syncthreads();
    }

    // ---- Final: w = 2C * (p0 - X*v), thread-per-row, coalesced out ----
    {
        const float4* sv4 = (const float4*)sv;
        const uint2* row = sx2 + ((size_t)tid * PITCHW >> 1);
        float acc = 0.f;
        #pragma unroll 8
        for (int i = 0; i < 32; i++) {
            uint2  xw = row[i];
            float4 v4 = sv4[i];
            float2 f0 = bf2f(xw.x);
            float2 f1 = bf2f(xw.y);
            acc += f0.x * v4.x + f0.y * v4.y + f1.x * v4.z + f1.y * v4.w;
        }
        out[(size_t)b * DN + tid] = TWO_C * (sp0[tid] - acc);
    }
}

extern "C" void kernel_launch(void* const* d_in, const int* in_sizes, int n_in,
                              void* d_out, int out_size) {
    (void)in_sizes; (void)n_in; (void)out_size;
    const float* X = (const float*)d_in[0];
    float* out = (float*)d_out;

    cudaFuncSetAttribute(rankpool_kernel,
                         cudaFuncAttributeMaxDynamicSharedMemorySize, SMEM_BYTES);
    rankpool_kernel<<<256, NTHREADS, SMEM_BYTES>>>(X, out);
}

// round 7
// speedup vs baseline: 4.2491x; 1.2932x over previous
#include <cuda_runtime.h>
#include <cuda_bf16.h>

// RankPooling via Woodbury + Neumann (R7: fused fp32 q1 in phase A, 2 terms,
// no v vector, 3 post-load smem passes).
//   w = 2C*(p0 - p1 + p2)
//   p0 = X*y          (fp32, fused into load)
//   t1 = 2C*X^T*p0    (fp32, partials fused into load)
//   p1 = X*t1         (bf16 smem)
//   t2 = 2C*X^T*p1    (bf16 smem)
//   p2 = X*t2         (bf16 smem)
// X[b]: [D=768, T=128] row-major. 24 warps, 1 CTA/SM, pitch-66 uint2 layout.

#define DN 768
#define TN 128
#define NW 24
#define NTHREADS 768
#define PITCHW 66   // 4B words per smem row (132 bf16, 264B); even -> uint2 aligned

// SMEM layout (bytes)
#define OFF_X   0          // bf16x2 words [768][66] = 202752
#define OFF_P   202752     // float[768]  (p1 = X*t1)        = 3072
#define OFF_P0  205824     // float[768]  (p0 = X*y fp32)    = 3072
#define OFF_QP  208896     // float[24][128]                 = 12288
#define OFF_U   221184     // float[128]                     = 512
#define SMEM_BYTES 221696

static __device__ __forceinline__ float warp_sum(float v) {
    v += __shfl_xor_sync(0xffffffffu, v, 16);
    v += __shfl_xor_sync(0xffffffffu, v, 8);
    v += __shfl_xor_sync(0xffffffffu, v, 4);
    v += __shfl_xor_sync(0xffffffffu, v, 2);
    v += __shfl_xor_sync(0xffffffffu, v, 1);
    return v;   // all lanes hold the total (xor butterfly)
}

static __device__ __forceinline__ float2 bf2f(unsigned w) {
    return __bfloat1622float2(*reinterpret_cast<__nv_bfloat162*>(&w));
}

__global__ void __launch_bounds__(NTHREADS, 1)
rankpool_kernel(const float* __restrict__ X, float* __restrict__ out) {
    extern __shared__ char smraw[];
    uint2* sx2 = (uint2*)(smraw + OFF_X);
    float* sp  = (float*)(smraw + OFF_P);
    float* sp0 = (float*)(smraw + OFF_P0);
    float* sqp = (float*)(smraw + OFF_QP);
    float* su  = (float*)(smraw + OFF_U);

    const int tid  = threadIdx.x;
    const int warp = tid >> 5;
    const int lane = tid & 31;
    const int b    = blockIdx.x;
    const float4* Xb4 = (const float4*)(X + (size_t)b * (DN * TN));
    const float TWO_C = 2e-5f;

    // y values this lane touches: t = 4*lane+1 .. 4*lane+4 (1-based)
    const float4 y4 = make_float4((float)(4 * lane + 1), (float)(4 * lane + 2),
                                  (float)(4 * lane + 3), (float)(4 * lane + 4));

    // ---- Phase A: stream X -> bf16 SMEM; fuse p0 = X*y and q1 = X^T*p0 ----
    {
        const int dbase = warp * 32;
        float4 qa = make_float4(0.f, 0.f, 0.f, 0.f);
        #pragma unroll 1
        for (int j = 0; j < 32; j += 8) {
            float4 xs[8];
            #pragma unroll
            for (int k = 0; k < 8; k++)
                xs[k] = Xb4[(dbase + j + k) * 32 + lane];
            #pragma unroll
            for (int k = 0; k < 8; k++) {
                const int d = dbase + j + k;
                __nv_bfloat162 lo = __float22bfloat162_rn(make_float2(xs[k].x, xs[k].y));
                __nv_bfloat162 hi = __float22bfloat162_rn(make_float2(xs[k].z, xs[k].w));
                uint2 pk;
                pk.x = *reinterpret_cast<unsigned*>(&lo);
                pk.y = *reinterpret_cast<unsigned*>(&hi);
                sx2[(d * PITCHW + 2 * lane) >> 1] = pk;
            }
            #pragma unroll
            for (int k = 0; k < 8; k++) {
                float part = xs[k].x * y4.x + xs[k].y * y4.y
                           + xs[k].z * y4.z + xs[k].w * y4.w;
                part = warp_sum(part);               // every lane holds p0[d]
                if (lane == 0) sp0[dbase + j + k] = part;
                qa.x += part * xs[k].x;              // fp32 q1 partial, in-register
                qa.y += part * xs[k].y;
                qa.z += part * xs[k].z;
                qa.w += part * xs[k].w;
            }
        }
        ((float4*)(sqp + warp * TN))[lane] = qa;
    }
    __syncthreads();

    // reduce q1 partials: t1 = 2C * q1
    if (tid < TN) {
        float q = 0.f;
        #pragma unroll
        for (int w = 0; w < NW; w++) q += sqp[w * TN + tid];
        su[tid] = TWO_C * q;
    }
    __syncthreads();

    // ---- Pass 1: p1 = X * t1 (thread-per-row, bf16 smem) ----
    float p1;
    {
        const float4* su4 = (const float4*)su;
        const uint2* row = sx2 + ((size_t)tid * PITCHW >> 1);
        float acc = 0.f;
        #pragma unroll 8
        for (int i = 0; i < 32; i++) {
            uint2  xw = row[i];
            float4 u4 = su4[i];
            float2 f0 = bf2f(xw.x);
            float2 f1 = bf2f(xw.y);
            acc += f0.x * u4.x + f0.y * u4.y + f1.x * u4.z + f1.y * u4.w;
        }
        p1 = acc;
        sp[tid] = acc;
    }
    __syncthreads();

    // ---- Pass 2: partial q2 = X^T * p1 (warp over its 32 rows) ----
    {
        float a0 = 0.f, a1 = 0.f, a2 = 0.f, a3 = 0.f;
        const int d0 = warp * 32;
        const uint2* rp = sx2 + ((size_t)d0 * PITCHW >> 1) + lane;
        #pragma unroll 8
        for (int dd = 0; dd < 32; dd++) {
            float pd = sp[d0 + dd];                  // uniform -> broadcast
            uint2 xw = rp[(size_t)dd * (PITCHW >> 1)];
            float2 f0 = bf2f(xw.x);
            float2 f1 = bf2f(xw.y);
            a0 += pd * f0.x; a1 += pd * f0.y;
            a2 += pd * f1.x; a3 += pd * f1.y;
        }
        ((float4*)(sqp + warp * TN))[lane] = make_float4(a0, a1, a2, a3);
    }
    __syncthreads();

    // reduce q2 partials: t2 = 2C * q2
    if (tid < TN) {
        float q = 0.f;
        #pragma unroll
        for (int w = 0; w < NW; w++) q += sqp[w * TN + tid];
        su[tid] = TWO_C * q;
    }
    __syncthreads();

    // ---- Pass 3: p2 = X * t2; output w = 2C*(p0 - p1 + p2), coalesced ----
    {
        const float4* su4 = (const float4*)su;
        const uint2* row = sx2 + ((size_t)tid * PITCHW >> 1);
        float acc = 0.f;
        #pragma unroll 8
        for (int i = 0; i < 32; i++) {
            uint2  xw = row[i];
            float4 u4 = su4[i];
            float2 f0 = bf2f(xw.x);
            float2 f1 = bf2f(xw.y);
            acc += f0.x * u4.x + f0.y * u4.y + f1.x * u4.z + f1.y * u4.w;
        }
        out[(size_t)b * DN + tid] = TWO_C * (sp0[tid] - p1 + acc);
    }
}

extern "C" void kernel_launch(void* const* d_in, const int* in_sizes, int n_in,
                              void* d_out, int out_size) {
    (void)in_sizes; (void)n_in; (void)out_size;
    const float* X = (const float*)d_in[0];
    float* out = (float*)d_out;

    cudaFuncSetAttribute(rankpool_kernel,
                         cudaFuncAttributeMaxDynamicSharedMemorySize, SMEM_BYTES);
    rankpool_kernel<<<256, NTHREADS, SMEM_BYTES>>>(X, out);
}